// round 6
// baseline (speedup 1.0000x reference)
#include <cuda_runtime.h>
#include <math.h>

// GRU problem constants
#define T_SEQ 1024
#define BATCH 32
#define HID   512
#define H3    1536   // 3*HID
#define LAYERS 3

// ---------------------------------------------------------------------------
// Scratch (device globals — no runtime allocation allowed)
// ---------------------------------------------------------------------------
__device__ float g_xi[2][T_SEQ][H3][BATCH];     // [dir][t][gate_row][batch]
__device__ float g_y[2][T_SEQ][BATCH][2 * HID]; // layer outputs (2 buffers)
__device__ float g_h[2][2][BATCH][HID];         // h double buffer [buf][dir][b][k]
__device__ int   g_flag[2][64];                 // per-dir, per-CTA epoch flags

// ---------------------------------------------------------------------------
// f32x2 packed-FMA helpers (sm_100+; only reachable via PTX)
// ---------------------------------------------------------------------------
__device__ __forceinline__ unsigned long long dup2(float x) {
    unsigned long long r;
    asm("mov.b64 %0, {%1, %1};" : "=l"(r) : "f"(x));
    return r;
}
__device__ __forceinline__ void ffma2(unsigned long long& d,
                                      unsigned long long a,
                                      unsigned long long b) {
    asm("fma.rn.f32x2 %0, %1, %2, %0;" : "+l"(d) : "l"(a), "l"(b));
}
__device__ __forceinline__ float2 unpk(unsigned long long v) {
    float2 f;
    asm("mov.b64 {%0, %1}, %2;" : "=f"(f.x), "=f"(f.y) : "l"(v));
    return f;
}

// ---------------------------------------------------------------------------
// Zero the flag array (runs once per graph replay, before gru0)
// ---------------------------------------------------------------------------
__global__ void zero_bar_kernel() {
    int i = threadIdx.x;
    if (i < 128) ((int*)g_flag)[i] = 0;
}

// ---------------------------------------------------------------------------
// Input projection: Xi[d][t][g][b] = sum_k A[(t,b),k] * W[d][g][k] + b_ih[d][g]
// 128x128x16 tile, 8x8 register tile per thread, f32x2 packed FMA.
// Thread's rows/cols split as {base, base+64} for conflict-free LDS.128.
// ---------------------------------------------------------------------------
__global__ __launch_bounds__(256, 2) void proj_kernel(
    const float* __restrict__ x0,
    const float* __restrict__ W,      // (2, 1536, K)
    const float* __restrict__ bih,    // (2, 1536)
    int K, int src)
{
    const float* A = (src == 0) ? x0 : &g_y[src - 1][0][0][0];

    int d  = blockIdx.z;
    int n0 = blockIdx.x * 128;  // gate-row tile
    int m0 = blockIdx.y * 128;  // (t,b) row tile
    const float* Wd = W + (size_t)d * H3 * K;
    const float* bd = bih + d * H3;

    __shared__ float As[16][128];
    __shared__ float Bs[16][128];

    int tid = threadIdx.x;
    int tx  = tid & 15;
    int ty  = tid >> 4;

    unsigned long long acc[8][4];
#pragma unroll
    for (int i = 0; i < 8; i++)
#pragma unroll
        for (int j = 0; j < 4; j++) acc[i][j] = 0ull;

    for (int k0 = 0; k0 < K; k0 += 16) {
#pragma unroll
        for (int i = 0; i < 2; i++) {
            int idx  = i * 256 + tid;      // float4 idx 0..511
            int lrow = idx >> 2;           // 0..127
            int lq   = (idx & 3) << 2;     // 0,4,8,12
            float4 a4 = *(const float4*)&A [(size_t)(m0 + lrow) * K + k0 + lq];
            float4 b4 = *(const float4*)&Wd[(size_t)(n0 + lrow) * K + k0 + lq];
            As[lq + 0][lrow] = a4.x; As[lq + 1][lrow] = a4.y;
            As[lq + 2][lrow] = a4.z; As[lq + 3][lrow] = a4.w;
            Bs[lq + 0][lrow] = b4.x; Bs[lq + 1][lrow] = b4.y;
            Bs[lq + 2][lrow] = b4.z; Bs[lq + 3][lrow] = b4.w;
        }
        __syncthreads();
#pragma unroll
        for (int kk = 0; kk < 16; kk++) {
            float4 af0 = *(const float4*)&As[kk][ty * 4];
            float4 af1 = *(const float4*)&As[kk][64 + ty * 4];
            ulonglong2 b0 = *(const ulonglong2*)&Bs[kk][tx * 4];
            ulonglong2 b1 = *(const ulonglong2*)&Bs[kk][64 + tx * 4];
            unsigned long long aa[8];
            aa[0] = dup2(af0.x); aa[1] = dup2(af0.y);
            aa[2] = dup2(af0.z); aa[3] = dup2(af0.w);
            aa[4] = dup2(af1.x); aa[5] = dup2(af1.y);
            aa[6] = dup2(af1.z); aa[7] = dup2(af1.w);
#pragma unroll
            for (int i = 0; i < 8; i++) {
                ffma2(acc[i][0], aa[i], b0.x);
                ffma2(acc[i][1], aa[i], b0.y);
                ffma2(acc[i][2], aa[i], b1.x);
                ffma2(acc[i][3], aa[i], b1.y);
            }
        }
        __syncthreads();
    }

#pragma unroll
    for (int i = 0; i < 8; i++) {
        int m = m0 + ((i < 4) ? (ty * 4 + i) : (64 + ty * 4 + (i - 4)));
        int t = m >> 5;
        int b = m & 31;
#pragma unroll
        for (int jp = 0; jp < 4; jp++) {
            int g = n0 + ((jp < 2) ? (tx * 4 + jp * 2)
                                   : (64 + tx * 4 + (jp - 2) * 2));
            float2 c = unpk(acc[i][jp]);
            g_xi[d][t][g + 0][b] = c.x + bd[g + 0];
            g_xi[d][t][g + 1][b] = c.y + bd[g + 1];
        }
    }
}

// ---------------------------------------------------------------------------
// Persistent recurrent kernel, t_j = 2:
// grid = (64, 2) = 128 CTAs (1/SM), 128 threads: warp w -> j-pair {j0+2w, +1},
// lanes = b. Each thread computes 2 j x 3 gates => h crossbar traffic halves
// (each lane still reads h[b][*] once, reused by 6 dot products).
// Grid sync: per-CTA epoch flags (plain release store + 64 pollers), no atomics.
// ---------------------------------------------------------------------------
#define P_H 516   // padded sH row (floats): lane stride 516 -> conflict-free f4
#define GRU_SMEM ((3 * 8 * 512 + BATCH * P_H) * 4)

__global__ __launch_bounds__(128) void gru_layer_kernel(
    const float* __restrict__ whh,   // (2, 1536, 512)
    const float* __restrict__ bhh,   // (2, 1536)
    float* __restrict__ dout,        // (6, 32, 512)
    int layer, int ydst)
{
    extern __shared__ float sm[];
    float* sW = sm;                  // [3][8][512]
    float* sH = sm + 3 * 8 * 512;    // [32][516]

    int d   = blockIdx.y;
    int j0  = blockIdx.x * 8;
    int tid = threadIdx.x;
    int b   = tid & 31;
    int w   = tid >> 5;              // 0..3 -> j-pair
    int ja  = j0 + 2 * w;

    // ---- Stage W_hh rows {j0..j0+7} x 3 gates (once per layer) ----
    const float* wd = whh + (size_t)d * H3 * HID;
#pragma unroll
    for (int it = 0; it < 24; it++) {
        int idx  = it * 128 + tid;       // float4 units, 0..3071
        int row  = idx >> 7;             // 0..23
        int q    = (idx & 127) << 2;
        int gate = row >> 3;
        int r    = row & 7;
        *(float4*)&sW[(gate * 8 + r) * 512 + q] =
            *(const float4*)&wd[(size_t)(gate * 512 + j0 + r) * 512 + q];
    }
    const float* bd = bhh + d * H3;
    float brA = bd[ja],        brB = bd[ja + 1];
    float bzA = bd[512 + ja],  bzB = bd[512 + ja + 1];
    float bnA = bd[1024 + ja], bnB = bd[1024 + ja + 1];

    const float* wrA = &sW[(0 * 8 + 2 * w) * 512];
    const float* wrB = wrA + 512;
    const float* wzA = &sW[(1 * 8 + 2 * w) * 512];
    const float* wzB = wzA + 512;
    const float* wnA = &sW[(2 * 8 + 2 * w) * 512];
    const float* wnB = wnA + 512;
    const float* hb  = &sH[b * P_H];
    __syncthreads();

    float holdA = 0.f, holdB = 0.f;
    int t0 = d ? (T_SEQ - 1) : 0;
    float xrA = g_xi[d][t0][ja][b],        xrB = g_xi[d][t0][ja + 1][b];
    float xzA = g_xi[d][t0][512 + ja][b],  xzB = g_xi[d][t0][512 + ja + 1][b];
    float xnA = g_xi[d][t0][1024 + ja][b], xnB = g_xi[d][t0][1024 + ja + 1][b];

    for (int s = 0; s < T_SEQ; s++) {
        int t = d ? (T_SEQ - 1 - s) : s;

        float arA = 0.f, azA = 0.f, anA = 0.f;
        float arB = 0.f, azB = 0.f, anB = 0.f;
        if (s > 0) {
            // Stage h (L2-coherent reads; written by other SMs last step)
            const float* hin = &g_h[s & 1][d][0][0];
#pragma unroll
            for (int it = 0; it < 32; it++) {
                int idx = it * 128 + tid;           // float4 units
                float4 v = __ldcg((const float4*)&hin[idx << 2]);
                int bb = idx >> 7;
                int kq = (idx & 127) << 2;
                *(float4*)&sH[bb * P_H + kq] = v;
            }
            __syncthreads();

            unsigned long long aA0 = 0, aA1 = 0, aA2 = 0;
            unsigned long long aB0 = 0, aB1 = 0, aB2 = 0;
#pragma unroll 4
            for (int k = 0; k < HID; k += 4) {
                ulonglong2 hh = *(const ulonglong2*)&hb[k];     // per-lane
                ulonglong2 r0 = *(const ulonglong2*)&wrA[k];    // broadcast
                ulonglong2 r1 = *(const ulonglong2*)&wrB[k];
                ulonglong2 z0 = *(const ulonglong2*)&wzA[k];
                ulonglong2 z1 = *(const ulonglong2*)&wzB[k];
                ulonglong2 n0 = *(const ulonglong2*)&wnA[k];
                ulonglong2 n1 = *(const ulonglong2*)&wnB[k];
                ffma2(aA0, r0.x, hh.x); ffma2(aA0, r0.y, hh.y);
                ffma2(aB0, r1.x, hh.x); ffma2(aB0, r1.y, hh.y);
                ffma2(aA1, z0.x, hh.x); ffma2(aA1, z0.y, hh.y);
                ffma2(aB1, z1.x, hh.x); ffma2(aB1, z1.y, hh.y);
                ffma2(aA2, n0.x, hh.x); ffma2(aA2, n0.y, hh.y);
                ffma2(aB2, n1.x, hh.x); ffma2(aB2, n1.y, hh.y);
            }
            float2 f;
            f = unpk(aA0); arA = f.x + f.y;
            f = unpk(aA1); azA = f.x + f.y;
            f = unpk(aA2); anA = f.x + f.y;
            f = unpk(aB0); arB = f.x + f.y;
            f = unpk(aB1); azB = f.x + f.y;
            f = unpk(aB2); anB = f.x + f.y;
        }

        float rA = 1.f / (1.f + expf(-(xrA + arA + brA)));
        float zA = 1.f / (1.f + expf(-(xzA + azA + bzA)));
        float nA = tanhf(xnA + rA * (anA + bnA));
        float hA = (1.f - zA) * nA + zA * holdA;
        holdA = hA;

        float rB = 1.f / (1.f + expf(-(xrB + arB + brB)));
        float zB = 1.f / (1.f + expf(-(xzB + azB + bzB)));
        float nB = tanhf(xnB + rB * (anB + bnB));
        float hB = (1.f - zB) * nB + zB * holdB;
        holdB = hB;

        g_h[(s & 1) ^ 1][d][b][ja]     = hA;
        g_h[(s & 1) ^ 1][d][b][ja + 1] = hB;
        g_y[ydst][t][b][d * HID + ja]     = hA;
        g_y[ydst][t][b][d * HID + ja + 1] = hB;

        if (s == T_SEQ - 1) {
            dout[((layer * 2 + d) * BATCH + b) * HID + ja]     = hA;
            dout[((layer * 2 + d) * BATCH + b) * HID + ja + 1] = hB;
            break;   // nothing consumes h after the last step
        }

        // ---- Grid barrier: per-CTA epoch flags (no atomic serialization) ----
        __syncthreads();                 // all h stores issued; sH reads done
        int e = layer * T_SEQ + s + 1;   // monotonic across layers
        if (tid == 0) {
            __threadfence();             // order this CTA's h stores
            *(volatile int*)&g_flag[d][blockIdx.x] = e;
        }
        // Prefetch next step's Xi while flags propagate
        int tn = d ? (T_SEQ - 2 - s) : (s + 1);
        float nxrA = g_xi[d][tn][ja][b],        nxrB = g_xi[d][tn][ja + 1][b];
        float nxzA = g_xi[d][tn][512 + ja][b],  nxzB = g_xi[d][tn][512 + ja + 1][b];
        float nxnA = g_xi[d][tn][1024 + ja][b], nxnB = g_xi[d][tn][1024 + ja + 1][b];
        if (tid < 64) {
            while (*(volatile int*)&g_flag[d][tid] < e) { }
        }
        __syncthreads();
        __threadfence();                 // acquire: order h reads after flags
        xrA = nxrA; xzA = nxzA; xnA = nxnA;
        xrB = nxrB; xzB = nxzB; xnB = nxnB;
    }
}

// ---------------------------------------------------------------------------
// kernel_launch: proj0, zero, zero(dummy), gru0, proj1, gru1, proj2, gru2
// (8 graph nodes; ncu -s 5 -c 1 lands on gru1)
// ---------------------------------------------------------------------------
extern "C" void kernel_launch(void* const* d_in, const int* in_sizes, int n_in,
                              void* d_out, int out_size)
{
    const float* x        = (const float*)d_in[0];
    const float* w_ih_l0  = (const float*)d_in[1];
    const float* w_hh_l0  = (const float*)d_in[2];
    const float* b_ih_l0  = (const float*)d_in[3];
    const float* b_hh_l0  = (const float*)d_in[4];
    const float* w_ih_lr  = (const float*)d_in[5];
    const float* w_hh_lr  = (const float*)d_in[6];
    const float* b_ih_lr  = (const float*)d_in[7];
    const float* b_hh_lr  = (const float*)d_in[8];
    float* out = (float*)d_out;

    cudaFuncSetAttribute(gru_layer_kernel,
                         cudaFuncAttributeMaxDynamicSharedMemorySize, GRU_SMEM);

    const float* WI[LAYERS];
    const float* WH[LAYERS];
    const float* BI[LAYERS];
    const float* BH[LAYERS];
    int KK[LAYERS], SRC[LAYERS], YD[LAYERS];
    for (int L = 0; L < LAYERS; L++) {
        if (L == 0) {
            WI[L] = w_ih_l0; WH[L] = w_hh_l0; BI[L] = b_ih_l0; BH[L] = b_hh_l0;
            KK[L] = 256; SRC[L] = 0;
        } else {
            WI[L] = w_ih_lr + (size_t)(L - 1) * 2 * H3 * 1024;
            WH[L] = w_hh_lr + (size_t)(L - 1) * 2 * H3 * HID;
            BI[L] = b_ih_lr + (L - 1) * 2 * H3;
            BH[L] = b_hh_lr + (L - 1) * 2 * H3;
            KK[L] = 1024; SRC[L] = L;
        }
        YD[L] = (L == 1) ? 1 : 0;   // L0->buf0, L1->buf1, L2->buf0 (unused)
    }

    dim3 pg(H3 / 128, (T_SEQ * BATCH) / 128, 2);

    proj_kernel<<<pg, 256>>>(x, WI[0], BI[0], KK[0], SRC[0]);
    zero_bar_kernel<<<1, 128>>>();
    zero_bar_kernel<<<1, 128>>>();   // dummy: aligns ncu -s 5 on gru1

    gru_layer_kernel<<<dim3(64, 2), 128, GRU_SMEM>>>(WH[0], BH[0], out, 0, YD[0]);
    proj_kernel<<<pg, 256>>>(x, WI[1], BI[1], KK[1], SRC[1]);
    gru_layer_kernel<<<dim3(64, 2), 128, GRU_SMEM>>>(WH[1], BH[1], out, 1, YD[1]);
    proj_kernel<<<pg, 256>>>(x, WI[2], BI[2], KK[2], SRC[2]);
    gru_layer_kernel<<<dim3(64, 2), 128, GRU_SMEM>>>(WH[2], BH[2], out, 2, YD[2]);
}

// round 8
// speedup vs baseline: 1.4467x; 1.4467x over previous
#include <cuda_runtime.h>
#include <math.h>

// GRU problem constants
#define T_SEQ 1024
#define BATCH 32
#define HID   512
#define H3    1536   // 3*HID
#define LAYERS 3

// ---------------------------------------------------------------------------
// Scratch (device globals — no runtime allocation allowed)
// ---------------------------------------------------------------------------
__device__ float g_xi[2][T_SEQ][H3][BATCH];     // [dir][t][gate_row][batch]
__device__ float g_y[2][T_SEQ][BATCH][2 * HID]; // layer outputs (2 buffers)
__device__ float g_h[2][2][BATCH][HID];         // h double buffer [buf][dir][b][k]
__device__ int   g_flag[2][64];                 // per-dir, per-CTA epoch flags

// ---------------------------------------------------------------------------
// f32x2 packed-FMA helpers (sm_100+; only reachable via PTX)
// ---------------------------------------------------------------------------
__device__ __forceinline__ unsigned long long dup2(float x) {
    unsigned long long r;
    asm("mov.b64 %0, {%1, %1};" : "=l"(r) : "f"(x));
    return r;
}
__device__ __forceinline__ void ffma2(unsigned long long& d,
                                      unsigned long long a,
                                      unsigned long long b) {
    asm("fma.rn.f32x2 %0, %1, %2, %0;" : "+l"(d) : "l"(a), "l"(b));
}
__device__ __forceinline__ float2 unpk(unsigned long long v) {
    float2 f;
    asm("mov.b64 {%0, %1}, %2;" : "=f"(f.x), "=f"(f.y) : "l"(v));
    return f;
}

// ---------------------------------------------------------------------------
// Zero the flag array (runs once per graph replay, before gru0)
// ---------------------------------------------------------------------------
__global__ void zero_bar_kernel() {
    int i = threadIdx.x;
    if (i < 128) ((int*)g_flag)[i] = 0;
}

// ---------------------------------------------------------------------------
// Input projection: Xi[d][t][g][b] = sum_k A[(t,b),k] * W[d][g][k] + b_ih[d][g]
// 128x128x16 tile, 8x8 register tile per thread, f32x2 packed FMA.
// ---------------------------------------------------------------------------
__global__ __launch_bounds__(256, 2) void proj_kernel(
    const float* __restrict__ x0,
    const float* __restrict__ W,      // (2, 1536, K)
    const float* __restrict__ bih,    // (2, 1536)
    int K, int src)
{
    const float* A = (src == 0) ? x0 : &g_y[src - 1][0][0][0];

    int d  = blockIdx.z;
    int n0 = blockIdx.x * 128;  // gate-row tile
    int m0 = blockIdx.y * 128;  // (t,b) row tile
    const float* Wd = W + (size_t)d * H3 * K;
    const float* bd = bih + d * H3;

    __shared__ float As[16][128];
    __shared__ float Bs[16][128];

    int tid = threadIdx.x;
    int tx  = tid & 15;
    int ty  = tid >> 4;

    unsigned long long acc[8][4];
#pragma unroll
    for (int i = 0; i < 8; i++)
#pragma unroll
        for (int j = 0; j < 4; j++) acc[i][j] = 0ull;

    for (int k0 = 0; k0 < K; k0 += 16) {
#pragma unroll
        for (int i = 0; i < 2; i++) {
            int idx  = i * 256 + tid;      // float4 idx 0..511
            int lrow = idx >> 2;           // 0..127
            int lq   = (idx & 3) << 2;     // 0,4,8,12
            float4 a4 = *(const float4*)&A [(size_t)(m0 + lrow) * K + k0 + lq];
            float4 b4 = *(const float4*)&Wd[(size_t)(n0 + lrow) * K + k0 + lq];
            As[lq + 0][lrow] = a4.x; As[lq + 1][lrow] = a4.y;
            As[lq + 2][lrow] = a4.z; As[lq + 3][lrow] = a4.w;
            Bs[lq + 0][lrow] = b4.x; Bs[lq + 1][lrow] = b4.y;
            Bs[lq + 2][lrow] = b4.z; Bs[lq + 3][lrow] = b4.w;
        }
        __syncthreads();
#pragma unroll
        for (int kk = 0; kk < 16; kk++) {
            float4 af0 = *(const float4*)&As[kk][ty * 4];
            float4 af1 = *(const float4*)&As[kk][64 + ty * 4];
            ulonglong2 b0 = *(const ulonglong2*)&Bs[kk][tx * 4];
            ulonglong2 b1 = *(const ulonglong2*)&Bs[kk][64 + tx * 4];
            unsigned long long aa[8];
            aa[0] = dup2(af0.x); aa[1] = dup2(af0.y);
            aa[2] = dup2(af0.z); aa[3] = dup2(af0.w);
            aa[4] = dup2(af1.x); aa[5] = dup2(af1.y);
            aa[6] = dup2(af1.z); aa[7] = dup2(af1.w);
#pragma unroll
            for (int i = 0; i < 8; i++) {
                ffma2(acc[i][0], aa[i], b0.x);
                ffma2(acc[i][1], aa[i], b0.y);
                ffma2(acc[i][2], aa[i], b1.x);
                ffma2(acc[i][3], aa[i], b1.y);
            }
        }
        __syncthreads();
    }

#pragma unroll
    for (int i = 0; i < 8; i++) {
        int m = m0 + ((i < 4) ? (ty * 4 + i) : (64 + ty * 4 + (i - 4)));
        int t = m >> 5;
        int b = m & 31;
#pragma unroll
        for (int jp = 0; jp < 4; jp++) {
            int g = n0 + ((jp < 2) ? (tx * 4 + jp * 2)
                                   : (64 + tx * 4 + (jp - 2) * 2));
            float2 c = unpk(acc[i][jp]);
            g_xi[d][t][g + 0][b] = c.x + bd[g + 0];
            g_xi[d][t][g + 1][b] = c.y + bd[g + 1];
        }
    }
}

// ---------------------------------------------------------------------------
// Persistent recurrent kernel. grid (64,2) = 128 CTAs (1/SM), 256 threads.
// 2-D lane mapping: lane = (lb 0..7 = batch, lj 0..3 = j-row); warp covers
// 8 b x 4 j; 8 warps tile (4 b-octets) x (2 j-quads) -> CTA = 32 b x 8 j.
// Both W rows (pad 516) and h rows (pad 516) hit ALL-DISTINCT banks:
//   h: 8 rows x 16B, bank starts {0,4,..,28} -> 1 phase (dedup x4 lanes)
//   W: 4 rows x 16B per gate -> 1 phase (dedup x8 lanes)
// => 4 crossbar phases / warp-iter (vs 7 in R5) with 2 warps/SMSP intact.
// ---------------------------------------------------------------------------
#define P_H 516   // padded row stride (floats) -> conflict-free LDS.128
#define GRU_SMEM ((3 * 8 * P_H + BATCH * P_H) * 4)

__global__ __launch_bounds__(256) void gru_layer_kernel(
    const float* __restrict__ whh,   // (2, 1536, 512)
    const float* __restrict__ bhh,   // (2, 1536)
    float* __restrict__ dout,        // (6, 32, 512)
    int layer, int ydst)
{
    extern __shared__ float sm[];
    float* sW = sm;                  // [3][8][516]
    float* sH = sm + 3 * 8 * P_H;    // [32][516]

    int d   = blockIdx.y;
    int j0  = blockIdx.x * 8;
    int tid = threadIdx.x;
    int w   = tid >> 5;
    int l   = tid & 31;
    int lb  = l & 7;
    int lj  = l >> 3;
    int b   = (w & 3) * 8 + lb;      // 0..31
    int jr  = (w >> 2) * 4 + lj;     // 0..7
    int j   = j0 + jr;

    // ---- Stage W_hh rows {j0..j0+7} x 3 gates (once per layer) ----
    const float* wd = whh + (size_t)d * H3 * HID;
#pragma unroll
    for (int it = 0; it < 12; it++) {
        int idx  = it * 256 + tid;       // float4 units, 0..3071
        int row  = idx >> 7;             // 0..23
        int q    = (idx & 127) << 2;
        int gate = row >> 3;
        int r    = row & 7;
        *(float4*)&sW[(gate * 8 + r) * P_H + q] =
            *(const float4*)&wd[(size_t)(gate * 512 + j0 + r) * 512 + q];
    }
    const float* bd = bhh + d * H3;
    float br = bd[j], bz = bd[512 + j], bn = bd[1024 + j];

    const float* wr_ = &sW[(0 * 8 + jr) * P_H];
    const float* wz_ = &sW[(1 * 8 + jr) * P_H];
    const float* wn_ = &sW[(2 * 8 + jr) * P_H];
    const float* hb  = &sH[b * P_H];
    __syncthreads();

    float hold = 0.f;
    int t0 = d ? (T_SEQ - 1) : 0;
    float xr = g_xi[d][t0][j][b];
    float xz = g_xi[d][t0][512 + j][b];
    float xn = g_xi[d][t0][1024 + j][b];

    for (int s = 0; s < T_SEQ; s++) {
        int t = d ? (T_SEQ - 1 - s) : s;

        float ar = 0.f, az = 0.f, an = 0.f;
        if (s > 0) {
            // Stage h: global [b][k] -> smem [b][k] (padded rows).
            // 32*512 floats = 4096 float4 units -> 16 iters * 256 threads.
            const float* hin = &g_h[s & 1][d][0][0];
#pragma unroll
            for (int it = 0; it < 16; it++) {
                int idx = it * 256 + tid;            // float4 units, 0..4095
                float4 v = __ldcg((const float4*)&hin[idx << 2]);
                int bb = idx >> 7;
                int kq = (idx & 127) << 2;
                *(float4*)&sH[bb * P_H + kq] = v;
            }
            __syncthreads();

            unsigned long long a0 = 0ull, a1 = 0ull, a2 = 0ull;
#pragma unroll 8
            for (int k = 0; k < HID; k += 4) {
                ulonglong2 hh = *(const ulonglong2*)&hb[k];
                ulonglong2 r2 = *(const ulonglong2*)&wr_[k];
                ulonglong2 z2 = *(const ulonglong2*)&wz_[k];
                ulonglong2 n2 = *(const ulonglong2*)&wn_[k];
                ffma2(a0, r2.x, hh.x); ffma2(a0, r2.y, hh.y);
                ffma2(a1, z2.x, hh.x); ffma2(a1, z2.y, hh.y);
                ffma2(a2, n2.x, hh.x); ffma2(a2, n2.y, hh.y);
            }
            float2 f;
            f = unpk(a0); ar = f.x + f.y;
            f = unpk(a1); az = f.x + f.y;
            f = unpk(a2); an = f.x + f.y;
        }

        float r = 1.f / (1.f + expf(-(xr + ar + br)));
        float z = 1.f / (1.f + expf(-(xz + az + bz)));
        float n = tanhf(xn + r * (an + bn));
        float hnew = (1.f - z) * n + z * hold;
        hold = hnew;

        g_h[(s & 1) ^ 1][d][b][j] = hnew;
        g_y[ydst][t][b][d * HID + j] = hnew;

        if (s == T_SEQ - 1) {
            dout[((layer * 2 + d) * BATCH + b) * HID + j] = hnew;
            break;   // nothing consumes h after the last step
        }

        // ---- Grid barrier: per-CTA epoch flags (no atomic serialization) ----
        __syncthreads();                 // all h stores issued; sH reads done
        int e = layer * T_SEQ + s + 1;   // monotonic across layers
        if (tid == 0) {
            __threadfence();             // order this CTA's h stores
            *(volatile int*)&g_flag[d][blockIdx.x] = e;
        }
        // Prefetch next step's Xi while flags propagate
        int tn = d ? (T_SEQ - 2 - s) : (s + 1);
        float nxr = g_xi[d][tn][j][b];
        float nxz = g_xi[d][tn][512 + j][b];
        float nxn = g_xi[d][tn][1024 + j][b];
        if (tid < 64) {
            while (*(volatile int*)&g_flag[d][tid] < e) { }
        }
        __syncthreads();
        __threadfence();                 // acquire: order h reads after flags
        xr = nxr; xz = nxz; xn = nxn;
    }
}

// ---------------------------------------------------------------------------
// kernel_launch: proj0, zero, zero(dummy), gru0, proj1, gru1, proj2, gru2
// (8 graph nodes; ncu -s 5 -c 1 lands on gru1)
// ---------------------------------------------------------------------------
extern "C" void kernel_launch(void* const* d_in, const int* in_sizes, int n_in,
                              void* d_out, int out_size)
{
    const float* x        = (const float*)d_in[0];
    const float* w_ih_l0  = (const float*)d_in[1];
    const float* w_hh_l0  = (const float*)d_in[2];
    const float* b_ih_l0  = (const float*)d_in[3];
    const float* b_hh_l0  = (const float*)d_in[4];
    const float* w_ih_lr  = (const float*)d_in[5];
    const float* w_hh_lr  = (const float*)d_in[6];
    const float* b_ih_lr  = (const float*)d_in[7];
    const float* b_hh_lr  = (const float*)d_in[8];
    float* out = (float*)d_out;

    cudaFuncSetAttribute(gru_layer_kernel,
                         cudaFuncAttributeMaxDynamicSharedMemorySize, GRU_SMEM);

    const float* WI[LAYERS];
    const float* WH[LAYERS];
    const float* BI[LAYERS];
    const float* BH[LAYERS];
    int KK[LAYERS], SRC[LAYERS], YD[LAYERS];
    for (int L = 0; L < LAYERS; L++) {
        if (L == 0) {
            WI[L] = w_ih_l0; WH[L] = w_hh_l0; BI[L] = b_ih_l0; BH[L] = b_hh_l0;
            KK[L] = 256; SRC[L] = 0;
        } else {
            WI[L] = w_ih_lr + (size_t)(L - 1) * 2 * H3 * 1024;
            WH[L] = w_hh_lr + (size_t)(L - 1) * 2 * H3 * HID;
            BI[L] = b_ih_lr + (L - 1) * 2 * H3;
            BH[L] = b_hh_lr + (L - 1) * 2 * H3;
            KK[L] = 1024; SRC[L] = L;
        }
        YD[L] = (L == 1) ? 1 : 0;   // L0->buf0, L1->buf1, L2->buf0 (unused)
    }

    dim3 pg(H3 / 128, (T_SEQ * BATCH) / 128, 2);

    proj_kernel<<<pg, 256>>>(x, WI[0], BI[0], KK[0], SRC[0]);
    zero_bar_kernel<<<1, 128>>>();
    zero_bar_kernel<<<1, 128>>>();   // dummy: aligns ncu -s 5 on gru1

    gru_layer_kernel<<<dim3(64, 2), 256, GRU_SMEM>>>(WH[0], BH[0], out, 0, YD[0]);
    proj_kernel<<<pg, 256>>>(x, WI[1], BI[1], KK[1], SRC[1]);
    gru_layer_kernel<<<dim3(64, 2), 256, GRU_SMEM>>>(WH[1], BH[1], out, 1, YD[1]);
    proj_kernel<<<pg, 256>>>(x, WI[2], BI[2], KK[2], SRC[2]);
    gru_layer_kernel<<<dim3(64, 2), 256, GRU_SMEM>>>(WH[2], BH[2], out, 2, YD[2]);
}